// round 3
// baseline (speedup 1.0000x reference)
#include <cuda_runtime.h>
#include <math.h>

// Problem constants
#define BN   4096
#define TN   512
#define ZD   64
#define OU   128
#define BERT 768
#define TOUT 513   // T+1 trajectory points

typedef unsigned long long ull;

// Scratch (device globals: no allocation allowed)
__device__ float gZaug[BN * ZD];
__device__ float gPartial[BN];

// ---------------------------------------------------------------------------
// f32x2 helpers
// ---------------------------------------------------------------------------
__device__ __forceinline__ void ffma2(ull& d, ull a, ull b) {
    asm("fma.rn.f32x2 %0, %1, %2, %0;" : "+l"(d) : "l"(a), "l"(b));
}
__device__ __forceinline__ float2 up2(ull v) {
    float2 f;
    asm("mov.b64 {%0, %1}, %2;" : "=f"(f.x), "=f"(f.y) : "l"(v));
    return f;
}
// tanh(x) = 1 - 2/(exp(2x)+1), via MUFU ex2 + fast divide. ~1e-6 rel err.
__device__ __forceinline__ float fast_tanh(float x) {
    float e;
    asm("ex2.approx.f32 %0, %1;" : "=f"(e) : "f"(x * 2.8853900817779268f));
    return 1.0f - __fdividef(2.0f, e + 1.0f);
}

// ---------------------------------------------------------------------------
// Phase A: warp-per-row. h = bert@projW + b -> LN -> +sigma*eps -> denoiser
// -> z_aug (scratch), diff partials, and t=0 outputs.
// ---------------------------------------------------------------------------
__global__ __launch_bounds__(256) void phaseA_kernel(
    const float* __restrict__ bert, const float* __restrict__ eps,
    const float* __restrict__ projW, const float* __restrict__ projB,
    const float* __restrict__ lnG, const float* __restrict__ lnB,
    const float* __restrict__ lns,
    const float* __restrict__ dW1, const float* __restrict__ db1,
    const float* __restrict__ dW2, const float* __restrict__ db2,
    const float* __restrict__ decW, const float* __restrict__ decB,
    float* __restrict__ outPd, float* __restrict__ outSl)
{
    const unsigned FULL = 0xffffffffu;
    int warp = (blockIdx.x * blockDim.x + threadIdx.x) >> 5;
    int l = threadIdx.x & 31;
    if (warp >= BN) return;
    const int r = warp;
    const int c = 2 * l;

    const float* brow = bert + (size_t)r * BERT;
    float hx = 0.f, hy = 0.f;
    #pragma unroll 4
    for (int k = 0; k < BERT; k++) {
        float bv = __ldg(brow + k);
        float2 wv = *(const float2*)(projW + k * ZD + c);
        hx = fmaf(bv, wv.x, hx);
        hy = fmaf(bv, wv.y, hy);
    }
    hx += projB[c]; hy += projB[c + 1];

    float s = hx + hy;
    #pragma unroll
    for (int o = 16; o; o >>= 1) s += __shfl_xor_sync(FULL, s, o);
    float mu = s * (1.0f / 64.0f);
    float d0 = hx - mu, d1 = hy - mu;
    float ss = d0 * d0 + d1 * d1;
    #pragma unroll
    for (int o = 16; o; o >>= 1) ss += __shfl_xor_sync(FULL, ss, o);
    float var = ss * (1.0f / 64.0f);
    float rs = rsqrtf(var + 1e-5f);
    float zc0 = d0 * rs * lnG[c]     + lnB[c];
    float zc1 = d1 * rs * lnG[c + 1] + lnB[c + 1];

    float sigma = log1pf(expf(lns[0]));
    float zn0 = zc0 + sigma * eps[(size_t)r * ZD + c];
    float zn1 = zc1 + sigma * eps[(size_t)r * ZD + c + 1];

    int j0 = 4 * l;
    float4 a = *(const float4*)(db1 + j0);
    #pragma unroll 4
    for (int k2 = 0; k2 < 32; k2++) {
        float zva = __shfl_sync(FULL, zn0, k2);
        float zvb = __shfl_sync(FULL, zn1, k2);
        int k = 2 * k2;
        float4 w = *(const float4*)(dW1 + k * OU + j0);
        a.x = fmaf(zva, w.x, a.x); a.y = fmaf(zva, w.y, a.y);
        a.z = fmaf(zva, w.z, a.z); a.w = fmaf(zva, w.w, a.w);
        w = *(const float4*)(dW1 + (k + 1) * OU + j0);
        a.x = fmaf(zvb, w.x, a.x); a.y = fmaf(zvb, w.y, a.y);
        a.z = fmaf(zvb, w.z, a.z); a.w = fmaf(zvb, w.w, a.w);
    }
    a.x = a.x / (1.f + expf(-a.x));
    a.y = a.y / (1.f + expf(-a.y));
    a.z = a.z / (1.f + expf(-a.z));
    a.w = a.w / (1.f + expf(-a.w));

    float za0 = db2[c], za1 = db2[c + 1];
    float a1v[4] = {a.x, a.y, a.z, a.w};
    #pragma unroll 2
    for (int k4 = 0; k4 < 32; k4++) {
        #pragma unroll
        for (int j = 0; j < 4; j++) {
            float hv = __shfl_sync(FULL, a1v[j], k4);
            int k = 4 * k4 + j;
            float2 w = *(const float2*)(dW2 + k * ZD + c);
            za0 = fmaf(hv, w.x, za0);
            za1 = fmaf(hv, w.y, za1);
        }
    }

    float dd = (za0 - zc0) * (za0 - zc0) + (za1 - zc1) * (za1 - zc1);
    #pragma unroll
    for (int o = 16; o; o >>= 1) dd += __shfl_xor_sync(FULL, dd, o);
    if (l == 0) gPartial[r] = dd;

    *(float2*)(gZaug + (size_t)r * ZD + c) = make_float2(za0, za1);

    float pd = za0 * decW[c * 2 + 0] + za1 * decW[(c + 1) * 2 + 0];
    float sl = za0 * decW[c * 2 + 1] + za1 * decW[(c + 1) * 2 + 1];
    #pragma unroll
    for (int o = 16; o; o >>= 1) {
        pd += __shfl_xor_sync(FULL, pd, o);
        sl += __shfl_xor_sync(FULL, sl, o);
    }
    if (l == 0) {
        outPd[(size_t)r * TOUT] = pd + decB[0];
        outSl[(size_t)r * TOUT] = sl + decB[1];
    }
}

// ---------------------------------------------------------------------------
// diff_loss final reduction (deterministic, single CTA)
// ---------------------------------------------------------------------------
__global__ void reduceDiff_kernel(float* __restrict__ outDiff)
{
    __shared__ float sh[256];
    float s = 0.f;
    for (int i = threadIdx.x; i < BN; i += 256) s += gPartial[i];
    sh[threadIdx.x] = s;
    __syncthreads();
    for (int step = 128; step; step >>= 1) {
        if (threadIdx.x < step) sh[threadIdx.x] += sh[threadIdx.x + step];
        __syncthreads();
    }
    if (threadIdx.x == 0) outDiff[0] = sh[0] * (1.0f / ((float)BN * (float)ZD));
}

// ---------------------------------------------------------------------------
// Phase B v2: f32x2-packed ODE scan.
// 128 CTAs x 256 threads; 32 rows/CTA; warp owns 4 rows.
// Lane = (rp = lane>>4, cg = lane&15): thread owns rows {4w+2rp, 4w+2rp+1}
// and 8 cols (G1/G2) / 4 cols (G3). Activations stored DUPLICATED in shared
// so packed broadcast operands come from a single ld.shared.b64 (no MOV packs).
// ---------------------------------------------------------------------------
#define ROWS 32

// gemm to 128 cols + tanh, dup in/out.
// sInDup: [row][2*KDIM], sW: [KDIM][128], sB: [128], sOutDup: [row][256]
template<int KDIM>
__device__ __forceinline__ void gemm_tanh128(
    const float* __restrict__ sInDup, const float* __restrict__ sW,
    const float* __restrict__ sB, float* __restrict__ sOutDup,
    int row0, int c8)
{
    ulonglong2 bA = *(const ulonglong2*)(sB + c8);
    ulonglong2 bB = *(const ulonglong2*)(sB + c8 + 4);
    ull acc[2][4];
    acc[0][0] = bA.x; acc[0][1] = bA.y; acc[0][2] = bB.x; acc[0][3] = bB.y;
    acc[1][0] = bA.x; acc[1][1] = bA.y; acc[1][2] = bB.x; acc[1][3] = bB.y;

    const float* in0 = sInDup + row0 * (2 * KDIM);
    const float* in1 = in0 + 2 * KDIM;

    #pragma unroll 4
    for (int k = 0; k < KDIM; k++) {
        ull z0 = *(const ull*)(in0 + 2 * k);
        ull z1 = *(const ull*)(in1 + 2 * k);
        ulonglong2 wA = *(const ulonglong2*)(sW + k * 128 + c8);
        ulonglong2 wB = *(const ulonglong2*)(sW + k * 128 + c8 + 4);
        ffma2(acc[0][0], z0, wA.x); ffma2(acc[0][1], z0, wA.y);
        ffma2(acc[0][2], z0, wB.x); ffma2(acc[0][3], z0, wB.y);
        ffma2(acc[1][0], z1, wA.x); ffma2(acc[1][1], z1, wA.y);
        ffma2(acc[1][2], z1, wB.x); ffma2(acc[1][3], z1, wB.y);
    }

    #pragma unroll
    for (int r = 0; r < 2; r++) {
        float* out = sOutDup + (row0 + r) * 256 + 2 * c8;
        #pragma unroll
        for (int j = 0; j < 4; j++) {
            float2 v = up2(acc[r][j]);
            float t0 = fast_tanh(v.x);
            float t1 = fast_tanh(v.y);
            *(float4*)(out + 4 * j) = make_float4(t0, t0, t1, t1);
        }
    }
}

__global__ __launch_bounds__(256, 1) void ode_kernel(
    const float* __restrict__ oW1, const float* __restrict__ ob1,
    const float* __restrict__ oW2, const float* __restrict__ ob2,
    const float* __restrict__ oW3, const float* __restrict__ ob3,
    const float* __restrict__ decW, const float* __restrict__ decB,
    float* __restrict__ outPd, float* __restrict__ outSl)
{
    extern __shared__ float sm[];
    float* sW1 = sm;                       // 64*128   = 8192
    float* sW2 = sW1 + ZD * OU;            // 128*128  = 16384
    float* sW3 = sW2 + OU * OU;            // 128*64   = 8192
    float* sB1 = sW3 + OU * ZD;            // 128
    float* sB2 = sB1 + OU;                 // 128
    float* sB3 = sB2 + OU;                 // 64
    float* sD0 = sB3 + ZD;                 // 64
    float* sD1 = sD0 + ZD;                 // 64
    float* sZd  = sD1 + ZD;                // 32*128 (dup)
    float* sH1d = sZd + ROWS * 2 * ZD;     // 32*256 (dup)
    float* sH2d = sH1d + ROWS * 2 * OU;    // 32*256 (dup)

    const int tid = threadIdx.x;
    const int rowBase = blockIdx.x * ROWS;

    // cooperative weight loads (float4)
    for (int i = tid; i < (ZD * OU) / 4; i += 256) ((float4*)sW1)[i] = ((const float4*)oW1)[i];
    for (int i = tid; i < (OU * OU) / 4; i += 256) ((float4*)sW2)[i] = ((const float4*)oW2)[i];
    for (int i = tid; i < (OU * ZD) / 4; i += 256) ((float4*)sW3)[i] = ((const float4*)oW3)[i];
    if (tid < OU) { sB1[tid] = ob1[tid]; sB2[tid] = ob2[tid]; }
    if (tid < ZD) { sB3[tid] = ob3[tid]; sD0[tid] = decW[2 * tid]; sD1[tid] = decW[2 * tid + 1]; }
    // z_aug -> duplicated shared
    for (int i = tid; i < ROWS * ZD; i += 256) {
        float v = gZaug[(size_t)rowBase * ZD + i];
        int row = i >> 6, c = i & 63;
        sZd[row * 128 + 2 * c]     = v;
        sZd[row * 128 + 2 * c + 1] = v;
    }
    __syncthreads();

    const int w    = tid >> 5;
    const int lane = tid & 31;
    const int rp   = lane >> 4;
    const int cg   = lane & 15;
    const int row0 = w * 4 + rp * 2;   // thread rows: row0, row0+1
    const int c8   = cg * 8;
    const int c4   = cg * 4;
    const float dt = 1.0f / (float)TN;
    const float db0 = decB[0], db1v = decB[1];
    const unsigned FULL = 0xffffffffu;
    const size_t gRow0 = (size_t)(rowBase + row0);

    const float4 dv0 = *(const float4*)(sD0 + c4);
    const float4 dv1 = *(const float4*)(sD1 + c4);
    const ulonglong2 b3 = *(const ulonglong2*)(sB3 + c4);

    for (int t = 0; t < TN; t++) {
        // ===== GEMM1: h1 = tanh(z @ W1 + b1), K=64 -> 128 cols =====
        gemm_tanh128<ZD>(sZd, sW1, sB1, sH1d, row0, c8);
        __syncwarp();

        // ===== GEMM2: h2 = tanh(h1 @ W2 + b2), K=128 -> 128 cols =====
        gemm_tanh128<OU>(sH1d, sW2, sB2, sH2d, row0, c8);
        __syncwarp();

        // ===== GEMM3: f = h2 @ W3 + b3 (64 cols), z update, decode =====
        {
            ull acc[2][2];
            acc[0][0] = b3.x; acc[0][1] = b3.y;
            acc[1][0] = b3.x; acc[1][1] = b3.y;
            const float* h0 = sH2d + row0 * 256;
            const float* h1 = h0 + 256;
            #pragma unroll 4
            for (int k = 0; k < OU; k++) {
                ull a0 = *(const ull*)(h0 + 2 * k);
                ull a1 = *(const ull*)(h1 + 2 * k);
                ulonglong2 wv = *(const ulonglong2*)(sW3 + k * ZD + c4);
                ffma2(acc[0][0], a0, wv.x); ffma2(acc[0][1], a0, wv.y);
                ffma2(acc[1][0], a1, wv.x); ffma2(acc[1][1], a1, wv.y);
            }
            #pragma unroll
            for (int r = 0; r < 2; r++) {
                float* zrow = sZd + (row0 + r) * 128 + 2 * c4;
                float4 za = *(const float4*)(zrow);       // z[c],z[c],z[c+1],z[c+1]
                float4 zb = *(const float4*)(zrow + 4);
                float2 f0 = up2(acc[r][0]);
                float2 f1 = up2(acc[r][1]);
                float z0 = fmaf(dt, f0.x, za.x);
                float z1 = fmaf(dt, f0.y, za.z);
                float z2 = fmaf(dt, f1.x, zb.x);
                float z3 = fmaf(dt, f1.y, zb.z);
                *(float4*)(zrow)     = make_float4(z0, z0, z1, z1);
                *(float4*)(zrow + 4) = make_float4(z2, z2, z3, z3);
                float pd = z0 * dv0.x + z1 * dv0.y + z2 * dv0.z + z3 * dv0.w;
                float sl = z0 * dv1.x + z1 * dv1.y + z2 * dv1.z + z3 * dv1.w;
                #pragma unroll
                for (int o = 8; o; o >>= 1) {
                    pd += __shfl_xor_sync(FULL, pd, o);
                    sl += __shfl_xor_sync(FULL, sl, o);
                }
                if (cg == 0) {
                    outPd[(gRow0 + r) * TOUT + t + 1] = pd + db0;
                    outSl[(gRow0 + r) * TOUT + t + 1] = sl + db1v;
                }
            }
            __syncwarp();
        }
    }
}

// ---------------------------------------------------------------------------
// Launch
// ---------------------------------------------------------------------------
extern "C" void kernel_launch(void* const* d_in, const int* in_sizes, int n_in,
                              void* d_out, int out_size)
{
    const float* bert  = (const float*)d_in[0];
    const float* eps   = (const float*)d_in[3];
    const float* projW = (const float*)d_in[4];
    const float* projB = (const float*)d_in[5];
    const float* lnG   = (const float*)d_in[6];
    const float* lnB   = (const float*)d_in[7];
    const float* lns   = (const float*)d_in[8];
    const float* dW1   = (const float*)d_in[9];
    const float* db1   = (const float*)d_in[10];
    const float* dW2   = (const float*)d_in[11];
    const float* db2   = (const float*)d_in[12];
    const float* oW1   = (const float*)d_in[13];
    const float* ob1   = (const float*)d_in[14];
    const float* oW2   = (const float*)d_in[15];
    const float* ob2   = (const float*)d_in[16];
    const float* oW3   = (const float*)d_in[17];
    const float* ob3   = (const float*)d_in[18];
    const float* decW  = (const float*)d_in[19];
    const float* decB  = (const float*)d_in[20];

    float* out    = (float*)d_out;
    float* outPd  = out;
    float* outSl  = out + (size_t)BN * TOUT;
    float* outDif = out + 2 * (size_t)BN * TOUT;

    phaseA_kernel<<<512, 256>>>(bert, eps, projW, projB, lnG, lnB, lns,
                                dW1, db1, dW2, db2, decW, decB, outPd, outSl);
    reduceDiff_kernel<<<1, 256>>>(outDif);

    size_t smemFloats = (size_t)(ZD * OU + OU * OU + OU * ZD          // weights
                                 + OU + OU + ZD + ZD + ZD             // biases + dec
                                 + ROWS * 2 * ZD                      // sZd (dup)
                                 + ROWS * 2 * OU + ROWS * 2 * OU);    // sH1d, sH2d (dup)
    size_t smemBytes = smemFloats * sizeof(float);
    cudaFuncSetAttribute(ode_kernel, cudaFuncAttributeMaxDynamicSharedMemorySize,
                         (int)smemBytes);
    ode_kernel<<<BN / ROWS, 256, smemBytes>>>(oW1, ob1, oW2, ob2, oW3, ob3,
                                              decW, decB, outPd, outSl);
}

// round 6
// speedup vs baseline: 2.4001x; 2.4001x over previous
#include <cuda_runtime.h>
#include <math.h>

// Problem constants
#define BN   4096
#define TN   512
#define ZD   64
#define OU   128
#define BERT 768
#define TOUT 513   // T+1 trajectory points
#define GRID 148
#define MAXROWS 28

// Scratch (device globals: no allocation allowed)
__device__ float gZaug[BN * ZD];
__device__ float gPartial[BN];

// tanh(x) = 1 - 2/(exp2(2x*log2e)+1). ex2 + fast divide — EXACT form validated
// on HW in R3 (rel_err 5.93e-7, unchanged vs tanhf).
__device__ __forceinline__ float fast_tanh(float x) {
    float e;
    asm("ex2.approx.f32 %0, %1;" : "=f"(e) : "f"(x * 2.8853900817779268f));
    return 1.0f - __fdividef(2.0f, e + 1.0f);
}

// ---------------------------------------------------------------------------
// Phase A: warp-per-row. h = bert@projW + b -> LN -> +sigma*eps -> denoiser
// -> z_aug (scratch), diff partials, and t=0 outputs.  (validated: ~110us)
// ---------------------------------------------------------------------------
__global__ __launch_bounds__(256) void phaseA_kernel(
    const float* __restrict__ bert, const float* __restrict__ eps,
    const float* __restrict__ projW, const float* __restrict__ projB,
    const float* __restrict__ lnG, const float* __restrict__ lnB,
    const float* __restrict__ lns,
    const float* __restrict__ dW1, const float* __restrict__ db1,
    const float* __restrict__ dW2, const float* __restrict__ db2,
    const float* __restrict__ decW, const float* __restrict__ decB,
    float* __restrict__ outPd, float* __restrict__ outSl)
{
    const unsigned FULL = 0xffffffffu;
    int warp = (blockIdx.x * blockDim.x + threadIdx.x) >> 5;
    int l = threadIdx.x & 31;
    if (warp >= BN) return;
    const int r = warp;
    const int c = 2 * l;

    const float* brow = bert + (size_t)r * BERT;
    float hx = 0.f, hy = 0.f;
    #pragma unroll 4
    for (int k = 0; k < BERT; k++) {
        float bv = __ldg(brow + k);
        float2 wv = *(const float2*)(projW + k * ZD + c);
        hx = fmaf(bv, wv.x, hx);
        hy = fmaf(bv, wv.y, hy);
    }
    hx += projB[c]; hy += projB[c + 1];

    float s = hx + hy;
    #pragma unroll
    for (int o = 16; o; o >>= 1) s += __shfl_xor_sync(FULL, s, o);
    float mu = s * (1.0f / 64.0f);
    float d0 = hx - mu, d1 = hy - mu;
    float ss = d0 * d0 + d1 * d1;
    #pragma unroll
    for (int o = 16; o; o >>= 1) ss += __shfl_xor_sync(FULL, ss, o);
    float var = ss * (1.0f / 64.0f);
    float rs = rsqrtf(var + 1e-5f);
    float zc0 = d0 * rs * lnG[c]     + lnB[c];
    float zc1 = d1 * rs * lnG[c + 1] + lnB[c + 1];

    float sigma = log1pf(expf(lns[0]));
    float zn0 = zc0 + sigma * eps[(size_t)r * ZD + c];
    float zn1 = zc1 + sigma * eps[(size_t)r * ZD + c + 1];

    int j0 = 4 * l;
    float4 a = *(const float4*)(db1 + j0);
    #pragma unroll 4
    for (int k2 = 0; k2 < 32; k2++) {
        float zva = __shfl_sync(FULL, zn0, k2);
        float zvb = __shfl_sync(FULL, zn1, k2);
        int k = 2 * k2;
        float4 w = *(const float4*)(dW1 + k * OU + j0);
        a.x = fmaf(zva, w.x, a.x); a.y = fmaf(zva, w.y, a.y);
        a.z = fmaf(zva, w.z, a.z); a.w = fmaf(zva, w.w, a.w);
        w = *(const float4*)(dW1 + (k + 1) * OU + j0);
        a.x = fmaf(zvb, w.x, a.x); a.y = fmaf(zvb, w.y, a.y);
        a.z = fmaf(zvb, w.z, a.z); a.w = fmaf(zvb, w.w, a.w);
    }
    a.x = a.x / (1.f + expf(-a.x));
    a.y = a.y / (1.f + expf(-a.y));
    a.z = a.z / (1.f + expf(-a.z));
    a.w = a.w / (1.f + expf(-a.w));

    float za0 = db2[c], za1 = db2[c + 1];
    float a1v[4] = {a.x, a.y, a.z, a.w};
    #pragma unroll 2
    for (int k4 = 0; k4 < 32; k4++) {
        #pragma unroll
        for (int j = 0; j < 4; j++) {
            float hv = __shfl_sync(FULL, a1v[j], k4);
            int k = 4 * k4 + j;
            float2 w = *(const float2*)(dW2 + k * ZD + c);
            za0 = fmaf(hv, w.x, za0);
            za1 = fmaf(hv, w.y, za1);
        }
    }

    float dd = (za0 - zc0) * (za0 - zc0) + (za1 - zc1) * (za1 - zc1);
    #pragma unroll
    for (int o = 16; o; o >>= 1) dd += __shfl_xor_sync(FULL, dd, o);
    if (l == 0) gPartial[r] = dd;

    *(float2*)(gZaug + (size_t)r * ZD + c) = make_float2(za0, za1);

    float pd = za0 * decW[c * 2 + 0] + za1 * decW[(c + 1) * 2 + 0];
    float sl = za0 * decW[c * 2 + 1] + za1 * decW[(c + 1) * 2 + 1];
    #pragma unroll
    for (int o = 16; o; o >>= 1) {
        pd += __shfl_xor_sync(FULL, pd, o);
        sl += __shfl_xor_sync(FULL, sl, o);
    }
    if (l == 0) {
        outPd[(size_t)r * TOUT] = pd + decB[0];
        outSl[(size_t)r * TOUT] = sl + decB[1];
    }
}

// ---------------------------------------------------------------------------
// diff_loss final reduction (deterministic, single CTA)
// ---------------------------------------------------------------------------
__global__ void reduceDiff_kernel(float* __restrict__ outDiff)
{
    __shared__ float sh[256];
    float s = 0.f;
    for (int i = threadIdx.x; i < BN; i += 256) s += gPartial[i];
    sh[threadIdx.x] = s;
    __syncthreads();
    for (int step = 128; step; step >>= 1) {
        if (threadIdx.x < step) sh[threadIdx.x] += sh[threadIdx.x + step];
        __syncthreads();
    }
    if (threadIdx.x == 0) outDiff[0] = sh[0] * (1.0f / ((float)BN * (float)ZD));
}

// ---------------------------------------------------------------------------
// Phase B: ODE scan, 148 CTAs (chip-filling). CTA 0..99: 28 rows; 100..147: 27.
// Warps own R in {3,4} rows, balanced so each SMSP (warps w,w+4) carries <=7
// rows. Warp-independent: no __syncthreads in the 512-step loop.
// ---------------------------------------------------------------------------
template<int R>
__device__ __forceinline__ void ode_loop(
    const float* __restrict__ sW1, const float* __restrict__ sW2,
    const float* __restrict__ sW3, const float* __restrict__ sB1,
    const float* __restrict__ sB2, const float* __restrict__ sB3,
    float* __restrict__ sZ, float* __restrict__ sH1, float* __restrict__ sH2,
    int row0, int l, size_t gRow0,
    float2 dv0, float2 dv1, float db0, float db1v,
    float* __restrict__ outPd, float* __restrict__ outSl)
{
    const int c4 = l * 4;
    const int c2 = l * 2;
    const float dt = 1.0f / (float)TN;
    const unsigned FULL = 0xffffffffu;

    for (int t = 0; t < TN; t++) {
        // ===== GEMM1: h1 = tanh(z @ W1 + b1), K=64 -> 128 cols =====
        {
            float4 acc[R];
            float4 bb = *(const float4*)(sB1 + c4);
            #pragma unroll
            for (int rr = 0; rr < R; rr++) acc[rr] = bb;
            #pragma unroll 2
            for (int k = 0; k < ZD; k += 4) {
                float4 zr[R];
                #pragma unroll
                for (int rr = 0; rr < R; rr++)
                    zr[rr] = *(const float4*)(sZ + (row0 + rr) * ZD + k);
                #pragma unroll
                for (int kk = 0; kk < 4; kk++) {
                    float4 wv = *(const float4*)(sW1 + (k + kk) * OU + c4);
                    #pragma unroll
                    for (int rr = 0; rr < R; rr++) {
                        float zv = (kk == 0) ? zr[rr].x : (kk == 1) ? zr[rr].y
                                 : (kk == 2) ? zr[rr].z : zr[rr].w;
                        acc[rr].x = fmaf(zv, wv.x, acc[rr].x);
                        acc[rr].y = fmaf(zv, wv.y, acc[rr].y);
                        acc[rr].z = fmaf(zv, wv.z, acc[rr].z);
                        acc[rr].w = fmaf(zv, wv.w, acc[rr].w);
                    }
                }
            }
            #pragma unroll
            for (int rr = 0; rr < R; rr++) {
                float4 v = acc[rr];
                v.x = fast_tanh(v.x); v.y = fast_tanh(v.y);
                v.z = fast_tanh(v.z); v.w = fast_tanh(v.w);
                *(float4*)(sH1 + (row0 + rr) * OU + c4) = v;
            }
            __syncwarp();
        }

        // ===== GEMM2: h2 = tanh(h1 @ W2 + b2), K=128 -> 128 cols =====
        {
            float4 acc[R];
            float4 bb = *(const float4*)(sB2 + c4);
            #pragma unroll
            for (int rr = 0; rr < R; rr++) acc[rr] = bb;
            #pragma unroll 2
            for (int k = 0; k < OU; k += 4) {
                float4 hr[R];
                #pragma unroll
                for (int rr = 0; rr < R; rr++)
                    hr[rr] = *(const float4*)(sH1 + (row0 + rr) * OU + k);
                #pragma unroll
                for (int kk = 0; kk < 4; kk++) {
                    float4 wv = *(const float4*)(sW2 + (k + kk) * OU + c4);
                    #pragma unroll
                    for (int rr = 0; rr < R; rr++) {
                        float hv = (kk == 0) ? hr[rr].x : (kk == 1) ? hr[rr].y
                                 : (kk == 2) ? hr[rr].z : hr[rr].w;
                        acc[rr].x = fmaf(hv, wv.x, acc[rr].x);
                        acc[rr].y = fmaf(hv, wv.y, acc[rr].y);
                        acc[rr].z = fmaf(hv, wv.z, acc[rr].z);
                        acc[rr].w = fmaf(hv, wv.w, acc[rr].w);
                    }
                }
            }
            #pragma unroll
            for (int rr = 0; rr < R; rr++) {
                float4 v = acc[rr];
                v.x = fast_tanh(v.x); v.y = fast_tanh(v.y);
                v.z = fast_tanh(v.z); v.w = fast_tanh(v.w);
                *(float4*)(sH2 + (row0 + rr) * OU + c4) = v;
            }
            __syncwarp();
        }

        // ===== GEMM3: f = h2 @ W3 + b3 (64 cols), z update, decode =====
        {
            float2 f[R];
            float2 b3v = *(const float2*)(sB3 + c2);
            #pragma unroll
            for (int rr = 0; rr < R; rr++) f[rr] = b3v;
            #pragma unroll 2
            for (int k = 0; k < OU; k += 4) {
                float4 hr[R];
                #pragma unroll
                for (int rr = 0; rr < R; rr++)
                    hr[rr] = *(const float4*)(sH2 + (row0 + rr) * OU + k);
                #pragma unroll
                for (int kk = 0; kk < 4; kk++) {
                    float2 wv = *(const float2*)(sW3 + (k + kk) * ZD + c2);
                    #pragma unroll
                    for (int rr = 0; rr < R; rr++) {
                        float hv = (kk == 0) ? hr[rr].x : (kk == 1) ? hr[rr].y
                                 : (kk == 2) ? hr[rr].z : hr[rr].w;
                        f[rr].x = fmaf(hv, wv.x, f[rr].x);
                        f[rr].y = fmaf(hv, wv.y, f[rr].y);
                    }
                }
            }
            float pd[R], sl[R];
            #pragma unroll
            for (int rr = 0; rr < R; rr++) {
                float2 zo = *(const float2*)(sZ + (row0 + rr) * ZD + c2);
                zo.x = fmaf(dt, f[rr].x, zo.x);
                zo.y = fmaf(dt, f[rr].y, zo.y);
                *(float2*)(sZ + (row0 + rr) * ZD + c2) = zo;
                pd[rr] = zo.x * dv0.x + zo.y * dv0.y;
                sl[rr] = zo.x * dv1.x + zo.y * dv1.y;
            }
            __syncwarp();
            #pragma unroll
            for (int rr = 0; rr < R; rr++) {
                float p = pd[rr], q = sl[rr];
                #pragma unroll
                for (int o = 16; o; o >>= 1) {
                    p += __shfl_xor_sync(FULL, p, o);
                    q += __shfl_xor_sync(FULL, q, o);
                }
                if (l == 0) {
                    size_t row = gRow0 + rr;
                    outPd[row * TOUT + (t + 1)] = p + db0;
                    outSl[row * TOUT + (t + 1)] = q + db1v;
                }
            }
        }
    }
}

// rows per warp: balanced so SMSP pairs (w, w+4) total <= 7 rows.
// cnt=28: {4,4,3,3,3,3,4,4}; cnt=27: {4,4,3,3,3,3,3,4}
__device__ __forceinline__ int rows_of(int w, int cnt) {
    if (cnt == 28) return (w <= 1 || w >= 6) ? 4 : 3;
    return (w <= 1 || w == 7) ? 4 : 3;
}

__global__ __launch_bounds__(256, 1) void ode_kernel(
    const float* __restrict__ oW1, const float* __restrict__ ob1,
    const float* __restrict__ oW2, const float* __restrict__ ob2,
    const float* __restrict__ oW3, const float* __restrict__ ob3,
    const float* __restrict__ decW, const float* __restrict__ decB,
    float* __restrict__ outPd, float* __restrict__ outSl)
{
    extern __shared__ float sm[];
    float* sW1 = sm;                       // 64*128
    float* sW2 = sW1 + ZD * OU;            // 128*128
    float* sW3 = sW2 + OU * OU;            // 128*64
    float* sB1 = sW3 + OU * ZD;            // 128
    float* sB2 = sB1 + OU;                 // 128
    float* sB3 = sB2 + OU;                 // 64
    float* sD0 = sB3 + ZD;                 // 64
    float* sD1 = sD0 + ZD;                 // 64
    float* sZ  = sD1 + ZD;                 // 28*64
    float* sH1 = sZ + MAXROWS * ZD;        // 28*128
    float* sH2 = sH1 + MAXROWS * OU;       // 28*128

    const int tid = threadIdx.x;
    const int cta = blockIdx.x;
    const int cnt     = (cta < 100) ? 28 : 27;
    const int rowBase = (cta < 100) ? 28 * cta : 2800 + 27 * (cta - 100);

    // cooperative weight/state loads (float4)
    for (int i = tid; i < (ZD * OU) / 4; i += 256) ((float4*)sW1)[i] = ((const float4*)oW1)[i];
    for (int i = tid; i < (OU * OU) / 4; i += 256) ((float4*)sW2)[i] = ((const float4*)oW2)[i];
    for (int i = tid; i < (OU * ZD) / 4; i += 256) ((float4*)sW3)[i] = ((const float4*)oW3)[i];
    if (tid < OU) { sB1[tid] = ob1[tid]; sB2[tid] = ob2[tid]; }
    if (tid < ZD) { sB3[tid] = ob3[tid]; sD0[tid] = decW[2 * tid]; sD1[tid] = decW[2 * tid + 1]; }
    for (int i = tid; i < cnt * (ZD / 4); i += 256)
        ((float4*)sZ)[i] = ((const float4*)(gZaug + (size_t)rowBase * ZD))[i];
    __syncthreads();

    const int w = tid >> 5;
    const int l = tid & 31;
    int row0 = 0;
    for (int j = 0; j < 8; j++) if (j < w) row0 += rows_of(j, cnt);
    const int R = rows_of(w, cnt);

    const int c2 = l * 2;
    const float2 dv0 = make_float2(sD0[c2], sD0[c2 + 1]);
    const float2 dv1 = make_float2(sD1[c2], sD1[c2 + 1]);
    const float db0 = decB[0], db1v = decB[1];
    const size_t gRow0 = (size_t)(rowBase + row0);

    if (R == 4)
        ode_loop<4>(sW1, sW2, sW3, sB1, sB2, sB3, sZ, sH1, sH2,
                    row0, l, gRow0, dv0, dv1, db0, db1v, outPd, outSl);
    else
        ode_loop<3>(sW1, sW2, sW3, sB1, sB2, sB3, sZ, sH1, sH2,
                    row0, l, gRow0, dv0, dv1, db0, db1v, outPd, outSl);
}

// ---------------------------------------------------------------------------
// Launch
// ---------------------------------------------------------------------------
extern "C" void kernel_launch(void* const* d_in, const int* in_sizes, int n_in,
                              void* d_out, int out_size)
{
    const float* bert  = (const float*)d_in[0];
    const float* eps   = (const float*)d_in[3];
    const float* projW = (const float*)d_in[4];
    const float* projB = (const float*)d_in[5];
    const float* lnG   = (const float*)d_in[6];
    const float* lnB   = (const float*)d_in[7];
    const float* lns   = (const float*)d_in[8];
    const float* dW1   = (const float*)d_in[9];
    const float* db1   = (const float*)d_in[10];
    const float* dW2   = (const float*)d_in[11];
    const float* db2   = (const float*)d_in[12];
    const float* oW1   = (const float*)d_in[13];
    const float* ob1   = (const float*)d_in[14];
    const float* oW2   = (const float*)d_in[15];
    const float* ob2   = (const float*)d_in[16];
    const float* oW3   = (const float*)d_in[17];
    const float* ob3   = (const float*)d_in[18];
    const float* decW  = (const float*)d_in[19];
    const float* decB  = (const float*)d_in[20];

    float* out    = (float*)d_out;
    float* outPd  = out;
    float* outSl  = out + (size_t)BN * TOUT;
    float* outDif = out + 2 * (size_t)BN * TOUT;

    phaseA_kernel<<<512, 256>>>(bert, eps, projW, projB, lnG, lnB, lns,
                                dW1, db1, dW2, db2, decW, decB, outPd, outSl);
    reduceDiff_kernel<<<1, 256>>>(outDif);

    size_t smemFloats = (size_t)(ZD * OU + OU * OU + OU * ZD        // weights
                                 + OU + OU + ZD + ZD + ZD           // biases + dec
                                 + MAXROWS * ZD + MAXROWS * OU + MAXROWS * OU);
    size_t smemBytes = smemFloats * sizeof(float);
    cudaFuncSetAttribute(ode_kernel, cudaFuncAttributeMaxDynamicSharedMemorySize,
                         (int)smemBytes);
    ode_kernel<<<GRID, 256, smemBytes>>>(oW1, ob1, oW2, ob2, oW3, ob3,
                                         decW, decB, outPd, outSl);
}